// round 14
// baseline (speedup 1.0000x reference)
#include <cuda_runtime.h>
#include <math.h>

// Geometry: N_LAYERS=12, H=12, Vq(L)=2+13L, Vm=Vq+12, layer size 37*Vq+12
#define NP      32936     // P_TOTAL
#define NLM     32778     // _LM_BASE
#define NV      158       // V_TOTAL
#define NLAY    12
#define NWORDS  1030      // ceil(NP/32)
#define NTHR    256
#define CHUNKF  1024      // floats per pipeline stage
#define NSTAGE  3
#define NST     33        // ceil(NP / CHUNKF)

__constant__ int c_lbase[NLAY] = {0, 86, 653, 1701, 3230, 5240, 7731,
                                  10703, 14156, 18090, 22505, 27401};

__device__ __align__(16) float g_pa[NP + 8];   // p*r + 0.5
__device__ __align__(16) float g_rw[NP + 8];   // 1/window

// ---------------------------------------------------------------------------
__global__ void precompute_kernel(const float* __restrict__ sp) {
    int i = blockIdx.x * blockDim.x + threadIdx.x;
    if (i >= NP) return;
    double pd = 1.0 / (1.0 + exp(-(double)sp[i]));
    float p = (float)pd;
    float w = p * (1.0f - p);
    float pp = w * p + (1.0f - w) * p;      // value == p (matches ref)
    float r  = __fdiv_rn(1.0f, w);
    g_rw[i] = r;
    g_pa[i] = fmaf(pp, r, 0.5f);            // mask = sat(A - u*r)
}

// ---------------------------------------------------------------------------
__device__ __forceinline__ unsigned ext32(const unsigned* P, int s) {
    return __funnelshift_r(P[s >> 5], P[(s >> 5) + 1], s & 31);
}
__device__ __forceinline__ unsigned lenmask(int n) {        // n in (0,32]
    return (n >= 32) ? 0xffffffffu : ((1u << n) - 1u);
}
__device__ __forceinline__ int getbit(const unsigned* B, int p) {
    return (B[p >> 5] >> (p & 31)) & 1;
}
__device__ __forceinline__ unsigned spread8(unsigned x) {   // 8 bits -> stride-4
    x &= 0xFFu;
    x = (x | (x << 12)) & 0x000F000Fu;
    x = (x | (x << 6))  & 0x03030303u;
    x = (x | (x << 3))  & 0x11111111u;
    return x;
}
__device__ __forceinline__ unsigned saddr(const void* p) {
    return (unsigned)__cvta_generic_to_shared(p);
}

#define MBWAIT(mb, par) do {                                                   \
    unsigned _d = 0;                                                           \
    while (!_d) {                                                              \
        asm volatile(                                                          \
            "{\n\t.reg .pred P;\n\t"                                          \
            "mbarrier.try_wait.parity.acquire.cta.shared::cta.b64 P, [%1], %2, 0x989680;\n\t" \
            "selp.b32 %0, 1, 0, P;\n\t}"                                      \
            : "=r"(_d) : "r"(mb), "r"(par) : "memory");                        \
    }                                                                          \
} while (0)

__device__ __forceinline__ void bulk_g2s(unsigned dst, const void* src,
                                         unsigned bytes, unsigned mb) {
    asm volatile(
        "cp.async.bulk.shared::cta.global.mbarrier::complete_tx::bytes [%0], [%1], %2, [%3];"
        :: "r"(dst), "l"(src), "r"(bytes), "r"(mb) : "memory");
}

// ---------------------------------------------------------------------------
__global__ __launch_bounds__(NTHR) void mask_kernel(const float* __restrict__ unif,
                                                    float* __restrict__ out) {
    __shared__ __align__(128) float4 sbuf[NSTAGE][3][CHUNKF / 4];
    __shared__ unsigned long long mbar[NSTAGE];
    __shared__ unsigned pos[NWORDS + 2];
    __shared__ unsigned sR[8];
    __shared__ unsigned sO[8];

    const int t = threadIdx.x, warp = t >> 5, lane = t & 31;
    const size_t rowoff = (size_t)blockIdx.x * NP;
    const float* urow = unif + rowoff;
    float4*      o4   = (float4*)(out + rowoff);
    float*       orow = out + rowoff;

    if (t < 8) { sR[t] = (t == 0) ? 3u : 0u; sO[t] = 0u; }
    if (t == 0) {
        pos[NWORDS] = 0u; pos[NWORDS + 1] = 0u;
        #pragma unroll
        for (int s = 0; s < NSTAGE; s++)
            asm volatile("mbarrier.init.shared.b64 [%0], 1;"
                         :: "r"(saddr(&mbar[s])) : "memory");
    }
    __syncthreads();

    // issue helper (single thread)
    auto issue = [&](int i) {
        int sl = i % NSTAGE;
        int e0 = i * CHUNKF;
        int n  = NP - e0; if (n > CHUNKF) n = CHUNKF;
        unsigned nb = (unsigned)n * 4u;
        unsigned mb = saddr(&mbar[sl]);
        asm volatile("mbarrier.arrive.expect_tx.shared.b64 _, [%0], %1;"
                     :: "r"(mb), "r"(3u * nb) : "memory");
        bulk_g2s(saddr(&sbuf[sl][0][0]), urow + e0, nb, mb);
        bulk_g2s(saddr(&sbuf[sl][1][0]), g_pa + e0, nb, mb);
        bulk_g2s(saddr(&sbuf[sl][2][0]), g_rw + e0, nb, mb);
    };

    if (t == 0) {
        issue(0); issue(1); issue(2);
    }

    // ---- Pass 1: pipelined stages ----
    for (int i = 0; i < NST; i++) {
        int sl = i % NSTAGE;
        int pr = (i / NSTAGE) & 1;
        MBWAIT(saddr(&mbar[sl]), pr);

        int e0 = i * CHUNKF;
        int n  = NP - e0; if (n > CHUNKF) n = CHUNKF;
        bool p0 = false, p1 = false, p2 = false, p3 = false;
        if (4 * t < n) {
            float4 u = sbuf[sl][0][t];
            float4 a = sbuf[sl][1][t];
            float4 r = sbuf[sl][2][t];
            float m0 = __saturatef(fmaf(-u.x, r.x, a.x));
            float m1 = __saturatef(fmaf(-u.y, r.y, a.y));
            float m2 = __saturatef(fmaf(-u.z, r.z, a.z));
            float m3 = __saturatef(fmaf(-u.w, r.w, a.w));
            __stcs(o4 + (256 * i + t), make_float4(m0, m1, m2, m3));
            p0 = m0 > 0.0f; p1 = m1 > 0.0f; p2 = m2 > 0.0f; p3 = m3 > 0.0f;
        }
        unsigned b0 = __ballot_sync(0xffffffffu, p0);
        unsigned b1 = __ballot_sync(0xffffffffu, p1);
        unsigned b2 = __ballot_sync(0xffffffffu, p2);
        unsigned b3 = __ballot_sync(0xffffffffu, p3);
        if (lane < 4) {
            int sh = 8 * lane;
            unsigned w = spread8(b0 >> sh)
                       | (spread8(b1 >> sh) << 1)
                       | (spread8(b2 >> sh) << 2)
                       | (spread8(b3 >> sh) << 3);
            int wi = 4 * (8 * i + warp) + lane;
            if (wi < NWORDS) pos[wi] = w;
        }
        __syncthreads();                       // all consumed -> slot reusable
        if (t == 0 && i + NSTAGE < NST) issue(i + NSTAGE);
    }

    // ---- Forward reachability R (warp 0, bit-parallel) ----
    if (warp == 0) {
        for (int L = 0; L < NLAY; L++) {
            const int Vq = 2 + 13 * L, b = c_lbase[L];
            unsigned acc1 = 0;
            {
                int s = b + lane * Vq;
                #pragma unroll
                for (int k = 0; k < 5; k++)
                    if (32 * k < Vq) acc1 |= ext32(pos, s + 32 * k) & sR[k];
            }
            bool a2 = false;
            if (lane < 4) {
                unsigned acc2 = 0;
                int s = b + (32 + lane) * Vq;
                #pragma unroll
                for (int k = 0; k < 5; k++)
                    if (32 * k < Vq) acc2 |= ext32(pos, s + 32 * k) & sR[k];
                a2 = acc2 != 0;
            }
            unsigned b1 = __ballot_sync(0xffffffffu, acc1 != 0);
            unsigned b2 = __ballot_sync(0xffffffffu, a2);
            if (lane == 0) {
                #pragma unroll
                for (int h = 0; h < 12; h++) {
                    unsigned q = (b1 >> h) & 1u;
                    unsigned kk = (b1 >> (12 + h)) & 1u;
                    unsigned v = (24 + h < 32) ? ((b1 >> (24 + h)) & 1u)
                                               : ((b2 >> (h - 8)) & 1u);
                    if (q & kk & v) { int p = Vq + h; sR[p >> 5] |= 1u << (p & 31); }
                }
            }
            __syncwarp();
            const int Vm = Vq + 12, sm = b + 36 * Vq;
            bool am = false;
            if (lane < 5 && 32 * lane < Vm)
                am = (ext32(pos, sm + 32 * lane) & sR[lane]) != 0;
            unsigned bm = __ballot_sync(0xffffffffu, am);
            if (lane == 0 && bm) sR[Vm >> 5] |= 1u << (Vm & 31);
            __syncwarp();
        }
        // ---- Backward reachability O on R-pruned graph (keep(R) folded) ----
        if (lane < 5) sO[lane] = ext32(pos, NLM + 32 * lane) & sR[lane] & lenmask(NV - 32 * lane);
        __syncwarp();
        for (int L = NLAY - 1; L >= 0; L--) {
            const int Vq = 2 + 13 * L, b = c_lbase[L], Vm = Vq + 12;
            int obm = getbit(sO, Vm) & getbit(sR, Vm);
            __syncwarp();
            if (obm && lane < 5 && 32 * lane < Vm)
                sO[lane] |= ext32(pos, b + 36 * Vq + 32 * lane) & sR[lane] & lenmask(Vm - 32 * lane);
            __syncwarp();
            unsigned wk[5] = {0, 0, 0, 0, 0};
            {
                int h = Vq + (lane % 12);
                if (getbit(sR, h) & getbit(sO, h)) {
                    int s = b + lane * Vq;
                    #pragma unroll
                    for (int k = 0; k < 5; k++)
                        if (32 * k < Vq) wk[k] = ext32(pos, s + 32 * k) & sR[k] & lenmask(Vq - 32 * k);
                }
            }
            if (lane < 4) {
                int h = Vq + ((32 + lane) % 12);
                if (getbit(sR, h) & getbit(sO, h)) {
                    int s = b + (32 + lane) * Vq;
                    #pragma unroll
                    for (int k = 0; k < 5; k++)
                        if (32 * k < Vq) wk[k] |= ext32(pos, s + 32 * k) & sR[k] & lenmask(Vq - 32 * k);
                }
            }
            #pragma unroll
            for (int k = 0; k < 5; k++) {
                unsigned red = __reduce_or_sync(0xffffffffu, wk[k]);
                if (lane == 0) sO[k] |= red;
            }
            __syncwarp();
        }
    }
    __syncthreads();

    // ---- Single final prune: kill = pos & ~(keepR & keepO) ----
    for (int g = t; g < 449; g += NTHR) {
        if (g < 444) {
            int L = g / 37, r = g % 37;
            int Vq = 2 + 13 * L, b = c_lbase[L];
            int s, len, hv;
            if (r < 36) { s = b + r * Vq; len = Vq; hv = Vq + (r % 12); }
            else        { s = b + 36 * Vq; len = Vq + 12; hv = Vq + 12; }
            int hk = getbit(sR, hv) & getbit(sO, hv);
            for (int k = 0; 32 * k < len; k++) {
                unsigned keep = hk ? (sR[k] & sO[k]) : 0u;
                unsigned kill = ext32(pos, s + 32 * k) & ~keep & lenmask(len - 32 * k);
                while (kill) {
                    int bp = __ffs(kill) - 1; kill &= kill - 1;
                    orow[s + 32 * k + bp] = 0.0f;
                }
            }
        } else {
            int k = g - 444;
            int s = NLM + 32 * k;
            unsigned kill = ext32(pos, s) & ~(sR[k] & sO[k]) & lenmask(NV - 32 * k);
            while (kill) {
                int bp = __ffs(kill) - 1; kill &= kill - 1;
                orow[s + bp] = 0.0f;
            }
        }
    }
}

// ---------------------------------------------------------------------------
extern "C" void kernel_launch(void* const* d_in, const int* in_sizes, int n_in,
                              void* d_out, int out_size) {
    const float* sp   = (const float*)d_in[0];
    const float* unif = (const float*)d_in[1];
    float*       out  = (float*)d_out;
    int bz = in_sizes[1] / NP;

    precompute_kernel<<<(NP + 255) / 256, 256>>>(sp);
    mask_kernel<<<bz, NTHR>>>(unif, out);
}

// round 15
// speedup vs baseline: 1.2165x; 1.2165x over previous
#include <cuda_runtime.h>
#include <math.h>

// Geometry: N_LAYERS=12, H=12, Vq(L)=2+13L, Vm=Vq+12, layer size 37*Vq+12
#define NP      32936     // P_TOTAL
#define NLM     32778     // _LM_BASE
#define NV      158       // V_TOTAL
#define NLAY    12
#define NWORDS  1030      // ceil(NP/32)
#define NTHR    256
#define NCHUNK  258       // 128-element chunks
#define NF4     8234      // NP/4 valid float4 indices
#define DEPTH   3         // per-warp cp.async ring depth

__constant__ int c_lbase[NLAY] = {0, 86, 653, 1701, 3230, 5240, 7731,
                                  10703, 14156, 18090, 22505, 27401};

__device__ __align__(16) float g_pa[NP + 8];   // p*r + 0.5
__device__ __align__(16) float g_rw[NP + 8];   // 1/window

// ---------------------------------------------------------------------------
__global__ void precompute_kernel(const float* __restrict__ sp) {
    int i = blockIdx.x * blockDim.x + threadIdx.x;
    if (i >= NP) return;
    double pd = 1.0 / (1.0 + exp(-(double)sp[i]));
    float p = (float)pd;
    float w = p * (1.0f - p);
    float pp = w * p + (1.0f - w) * p;      // value == p (matches ref)
    float r  = __fdiv_rn(1.0f, w);
    g_rw[i] = r;
    g_pa[i] = fmaf(pp, r, 0.5f);            // mask = sat(A - u*r)
}

// ---------------------------------------------------------------------------
__device__ __forceinline__ unsigned ext32(const unsigned* P, int s) {
    return __funnelshift_r(P[s >> 5], P[(s >> 5) + 1], s & 31);
}
__device__ __forceinline__ unsigned lenmask(int n) {        // n in (0,32]
    return (n >= 32) ? 0xffffffffu : ((1u << n) - 1u);
}
__device__ __forceinline__ int getbit(const unsigned* B, int p) {
    return (B[p >> 5] >> (p & 31)) & 1;
}
__device__ __forceinline__ unsigned spread8(unsigned x) {   // 8 bits -> stride-4
    x &= 0xFFu;
    x = (x | (x << 12)) & 0x000F000Fu;
    x = (x | (x << 6))  & 0x03030303u;
    x = (x | (x << 3))  & 0x11111111u;
    return x;
}
__device__ __forceinline__ unsigned saddr(const void* p) {
    return (unsigned)__cvta_generic_to_shared(p);
}
__device__ __forceinline__ void cpasync16(unsigned dst, const void* src, bool valid) {
    int sz = valid ? 16 : 0;                 // src-size 0 -> zero-fill
    asm volatile("cp.async.cg.shared.global [%0], [%1], 16, %2;"
                 :: "r"(dst), "l"(src), "r"(sz) : "memory");
}
#define CPCOMMIT() asm volatile("cp.async.commit_group;" ::: "memory")
#define CPWAIT(n)  asm volatile("cp.async.wait_group %0;" :: "n"(n) : "memory")

// ---------------------------------------------------------------------------
__global__ __launch_bounds__(NTHR, 8) void mask_kernel(const float* __restrict__ unif,
                                                       float* __restrict__ out) {
    __shared__ __align__(16) float4 uring[8][DEPTH][32];   // per-warp u rings
    __shared__ unsigned pos[NWORDS + 2];
    __shared__ unsigned sR[8];
    __shared__ unsigned sO[8];

    const int t = threadIdx.x, warp = t >> 5, lane = t & 31;
    const size_t rowoff = (size_t)blockIdx.x * NP;
    const float4* u4  = (const float4*)(unif + rowoff);
    float4*       o4  = (float4*)(out + rowoff);
    const float4* pa4 = (const float4*)g_pa;
    const float4* rw4 = (const float4*)g_rw;
    float*        orow = out + rowoff;

    if (t < 8) { sR[t] = (t == 0) ? 3u : 0u; sO[t] = 0u; }
    if (t == 0) { pos[NWORDS] = 0u; pos[NWORDS + 1] = 0u; }

    // ---- Pass 1: per-warp cp.async pipeline for u; pa/rw via L2 __ldg ----
    const int K = (NCHUNK - 1 - warp) / 8 + 1;       // chunks for this warp
    // prologue: fill ring
    #pragma unroll
    for (int d = 0; d < DEPTH; d++) {
        if (d < K) {
            int f = 32 * (warp + 8 * d) + lane;
            cpasync16(saddr(&uring[warp][d][lane]), u4 + f, f < NF4);
        }
        CPCOMMIT();
    }
    int sl = 0;
    for (int k = 0; k < K; k++) {
        const int c = warp + 8 * k;
        const int f = 32 * c + lane;
        CPWAIT(DEPTH - 1);                           // oldest group complete
        float4 u = uring[warp][sl][lane];
        bool p0 = false, p1 = false, p2 = false, p3 = false;
        if (f < NF4) {
            float4 a = __ldg(pa4 + f);
            float4 r = __ldg(rw4 + f);
            float m0 = __saturatef(fmaf(-u.x, r.x, a.x));
            float m1 = __saturatef(fmaf(-u.y, r.y, a.y));
            float m2 = __saturatef(fmaf(-u.z, r.z, a.z));
            float m3 = __saturatef(fmaf(-u.w, r.w, a.w));
            __stcs(o4 + f, make_float4(m0, m1, m2, m3));
            p0 = m0 > 0.0f; p1 = m1 > 0.0f; p2 = m2 > 0.0f; p3 = m3 > 0.0f;
        }
        unsigned b0 = __ballot_sync(0xffffffffu, p0);
        unsigned b1 = __ballot_sync(0xffffffffu, p1);
        unsigned b2 = __ballot_sync(0xffffffffu, p2);
        unsigned b3 = __ballot_sync(0xffffffffu, p3);
        if (lane < 4) {
            int sh = 8 * lane;
            unsigned w = spread8(b0 >> sh)
                       | (spread8(b1 >> sh) << 1)
                       | (spread8(b2 >> sh) << 2)
                       | (spread8(b3 >> sh) << 3);
            int wi = 4 * c + lane;
            if (wi < NWORDS) pos[wi] = w;
        }
        // refill consumed slot with chunk k+DEPTH
        int kn = k + DEPTH;
        if (kn < K) {
            int fn = 32 * (warp + 8 * kn) + lane;
            cpasync16(saddr(&uring[warp][sl][lane]), u4 + fn, fn < NF4);
        }
        CPCOMMIT();
        sl = (sl == DEPTH - 1) ? 0 : sl + 1;
    }
    __syncthreads();

    // ---- Forward reachability R (warp 0, bit-parallel) ----
    if (warp == 0) {
        for (int L = 0; L < NLAY; L++) {
            const int Vq = 2 + 13 * L, b = c_lbase[L];
            unsigned acc1 = 0;
            {
                int s = b + lane * Vq;
                #pragma unroll
                for (int k = 0; k < 5; k++)
                    if (32 * k < Vq) acc1 |= ext32(pos, s + 32 * k) & sR[k];
            }
            bool a2 = false;
            if (lane < 4) {
                unsigned acc2 = 0;
                int s = b + (32 + lane) * Vq;
                #pragma unroll
                for (int k = 0; k < 5; k++)
                    if (32 * k < Vq) acc2 |= ext32(pos, s + 32 * k) & sR[k];
                a2 = acc2 != 0;
            }
            unsigned b1 = __ballot_sync(0xffffffffu, acc1 != 0);
            unsigned b2 = __ballot_sync(0xffffffffu, a2);
            if (lane == 0) {
                #pragma unroll
                for (int h = 0; h < 12; h++) {
                    unsigned q = (b1 >> h) & 1u;
                    unsigned kk = (b1 >> (12 + h)) & 1u;
                    unsigned v = (24 + h < 32) ? ((b1 >> (24 + h)) & 1u)
                                               : ((b2 >> (h - 8)) & 1u);
                    if (q & kk & v) { int p = Vq + h; sR[p >> 5] |= 1u << (p & 31); }
                }
            }
            __syncwarp();
            const int Vm = Vq + 12, sm = b + 36 * Vq;
            bool am = false;
            if (lane < 5 && 32 * lane < Vm)
                am = (ext32(pos, sm + 32 * lane) & sR[lane]) != 0;
            unsigned bm = __ballot_sync(0xffffffffu, am);
            if (lane == 0 && bm) sR[Vm >> 5] |= 1u << (Vm & 31);
            __syncwarp();
        }
        // ---- Backward reachability O on R-pruned graph (keep(R) folded) ----
        if (lane < 5) sO[lane] = ext32(pos, NLM + 32 * lane) & sR[lane] & lenmask(NV - 32 * lane);
        __syncwarp();
        for (int L = NLAY - 1; L >= 0; L--) {
            const int Vq = 2 + 13 * L, b = c_lbase[L], Vm = Vq + 12;
            int obm = getbit(sO, Vm) & getbit(sR, Vm);
            __syncwarp();
            if (obm && lane < 5 && 32 * lane < Vm)
                sO[lane] |= ext32(pos, b + 36 * Vq + 32 * lane) & sR[lane] & lenmask(Vm - 32 * lane);
            __syncwarp();
            unsigned wk[5] = {0, 0, 0, 0, 0};
            {
                int h = Vq + (lane % 12);
                if (getbit(sR, h) & getbit(sO, h)) {
                    int s = b + lane * Vq;
                    #pragma unroll
                    for (int k = 0; k < 5; k++)
                        if (32 * k < Vq) wk[k] = ext32(pos, s + 32 * k) & sR[k] & lenmask(Vq - 32 * k);
                }
            }
            if (lane < 4) {
                int h = Vq + ((32 + lane) % 12);
                if (getbit(sR, h) & getbit(sO, h)) {
                    int s = b + (32 + lane) * Vq;
                    #pragma unroll
                    for (int k = 0; k < 5; k++)
                        if (32 * k < Vq) wk[k] |= ext32(pos, s + 32 * k) & sR[k] & lenmask(Vq - 32 * k);
                }
            }
            #pragma unroll
            for (int k = 0; k < 5; k++) {
                unsigned red = __reduce_or_sync(0xffffffffu, wk[k]);
                if (lane == 0) sO[k] |= red;
            }
            __syncwarp();
        }
    }
    __syncthreads();

    // ---- Single final prune: kill = pos & ~(keepR & keepO) ----
    for (int g = t; g < 449; g += NTHR) {
        if (g < 444) {
            int L = g / 37, r = g % 37;
            int Vq = 2 + 13 * L, b = c_lbase[L];
            int s, len, hv;
            if (r < 36) { s = b + r * Vq; len = Vq; hv = Vq + (r % 12); }
            else        { s = b + 36 * Vq; len = Vq + 12; hv = Vq + 12; }
            int hk = getbit(sR, hv) & getbit(sO, hv);
            for (int k = 0; 32 * k < len; k++) {
                unsigned keep = hk ? (sR[k] & sO[k]) : 0u;
                unsigned kill = ext32(pos, s + 32 * k) & ~keep & lenmask(len - 32 * k);
                while (kill) {
                    int bp = __ffs(kill) - 1; kill &= kill - 1;
                    orow[s + 32 * k + bp] = 0.0f;
                }
            }
        } else {
            int k = g - 444;
            int s = NLM + 32 * k;
            unsigned kill = ext32(pos, s) & ~(sR[k] & sO[k]) & lenmask(NV - 32 * k);
            while (kill) {
                int bp = __ffs(kill) - 1; kill &= kill - 1;
                orow[s + bp] = 0.0f;
            }
        }
    }
}

// ---------------------------------------------------------------------------
extern "C" void kernel_launch(void* const* d_in, const int* in_sizes, int n_in,
                              void* d_out, int out_size) {
    const float* sp   = (const float*)d_in[0];
    const float* unif = (const float*)d_in[1];
    float*       out  = (float*)d_out;
    int bz = in_sizes[1] / NP;

    precompute_kernel<<<(NP + 255) / 256, 256>>>(sp);
    mask_kernel<<<bz, NTHR>>>(unif, out);
}

// round 17
// speedup vs baseline: 1.2397x; 1.0190x over previous
#include <cuda_runtime.h>
#include <math.h>

// Geometry: N_LAYERS=12, H=12, Vq(L)=2+13L, Vm=Vq+12, layer size 37*Vq+12
#define NP      32936     // P_TOTAL
#define NLM     32778     // _LM_BASE
#define NV      158       // V_TOTAL
#define NLAY    12
#define NWORDS  1030      // ceil(NP/32)
#define NTHR    256
#define NCHUNK  258       // 128-element chunks
#define NF4     8234      // NP/4 valid float4 indices
#define DEPTH   3         // per-warp cp.async ring depth

__constant__ int c_lbase[NLAY] = {0, 86, 653, 1701, 3230, 5240, 7731,
                                  10703, 14156, 18090, 22505, 27401};

__device__ __align__(16) float g_pa[NP + 8];   // p*r + 0.5
__device__ __align__(16) float g_rw[NP + 8];   // 1/window

// ---------------------------------------------------------------------------
// fp32 precompute: expf differs from fp64-canonical by <=2ulp in p; boundary
// flips are value-irrelevant (flipped elements are ~0 either way).
__global__ void precompute_kernel(const float* __restrict__ sp) {
    int i = blockIdx.x * blockDim.x + threadIdx.x;
    if (i >= NP) return;
    float x = sp[i];
    float p = 1.0f / (1.0f + expf(-x));
    float w = p * (1.0f - p);
    float pp = w * p + (1.0f - w) * p;      // value == p (matches ref formula)
    float r  = __fdiv_rn(1.0f, w);
    g_rw[i] = r;
    g_pa[i] = fmaf(pp, r, 0.5f);            // mask = sat(A - u*r)
}

// ---------------------------------------------------------------------------
__device__ __forceinline__ unsigned ext32(const unsigned* P, int s) {
    return __funnelshift_r(P[s >> 5], P[(s >> 5) + 1], s & 31);
}
__device__ __forceinline__ unsigned lenmask(int n) {        // n in (0,32]
    return (n >= 32) ? 0xffffffffu : ((1u << n) - 1u);
}
__device__ __forceinline__ int getbit(const unsigned* B, int p) {
    return (B[p >> 5] >> (p & 31)) & 1;
}
__device__ __forceinline__ unsigned spread8(unsigned x) {   // 8 bits -> stride-4
    x &= 0xFFu;
    x = (x | (x << 12)) & 0x000F000Fu;
    x = (x | (x << 6))  & 0x03030303u;
    x = (x | (x << 3))  & 0x11111111u;
    return x;
}
__device__ __forceinline__ unsigned saddr(const void* p) {
    return (unsigned)__cvta_generic_to_shared(p);
}
__device__ __forceinline__ void cpasync16(unsigned dst, const void* src, bool valid) {
    int sz = valid ? 16 : 0;                 // src-size 0 -> zero-fill
    asm volatile("cp.async.cg.shared.global [%0], [%1], 16, %2;"
                 :: "r"(dst), "l"(src), "r"(sz) : "memory");
}
#define CPCOMMIT() asm volatile("cp.async.commit_group;" ::: "memory")
#define CPWAIT(n)  asm volatile("cp.async.wait_group %0;" :: "n"(n) : "memory")

// ---------------------------------------------------------------------------
__global__ __launch_bounds__(NTHR, 7) void mask_kernel(const float* __restrict__ unif,
                                                       float* __restrict__ out) {
    __shared__ __align__(16) float4 uring[8][DEPTH][32];   // per-warp u rings
    __shared__ unsigned pos[NWORDS + 2];
    __shared__ unsigned sR[8];
    __shared__ unsigned sO[8];

    const int t = threadIdx.x, warp = t >> 5, lane = t & 31;
    const size_t rowoff = (size_t)blockIdx.x * NP;
    const float4* u4  = (const float4*)(unif + rowoff);
    float4*       o4  = (float4*)(out + rowoff);
    const float4* pa4 = (const float4*)g_pa;
    const float4* rw4 = (const float4*)g_rw;
    float*        orow = out + rowoff;

    if (t < 8) { sR[t] = (t == 0) ? 3u : 0u; sO[t] = 0u; }
    if (t == 0) { pos[NWORDS] = 0u; pos[NWORDS + 1] = 0u; }

    // ---- Pass 1: per-warp cp.async ring for u; pa/rw prefetched 1 chunk ----
    const int K = (NCHUNK - 1 - warp) / 8 + 1;       // chunks for this warp
    #pragma unroll
    for (int d = 0; d < DEPTH; d++) {
        if (d < K) {
            int f = 32 * (warp + 8 * d) + lane;
            cpasync16(saddr(&uring[warp][d][lane]), u4 + f, f < NF4);
        }
        CPCOMMIT();
    }
    // prefetch tables for chunk 0
    float4 aN, rN;
    {
        int f0 = 32 * warp + lane;
        if (f0 < NF4) { aN = __ldg(pa4 + f0); rN = __ldg(rw4 + f0); }
    }
    int sl = 0;
    for (int k = 0; k < K; k++) {
        const int c = warp + 8 * k;
        const int f = 32 * c + lane;
        float4 a = aN, r = rN;
        // prefetch next chunk's tables BEFORE stalling on the u-wait
        if (k + 1 < K) {
            int fn = f + 256;
            if (fn < NF4) { aN = __ldg(pa4 + fn); rN = __ldg(rw4 + fn); }
        }
        CPWAIT(DEPTH - 1);                           // oldest u group complete
        float4 u = uring[warp][sl][lane];
        bool p0 = false, p1 = false, p2 = false, p3 = false;
        if (f < NF4) {
            float m0 = __saturatef(fmaf(-u.x, r.x, a.x));
            float m1 = __saturatef(fmaf(-u.y, r.y, a.y));
            float m2 = __saturatef(fmaf(-u.z, r.z, a.z));
            float m3 = __saturatef(fmaf(-u.w, r.w, a.w));
            __stcs(o4 + f, make_float4(m0, m1, m2, m3));
            p0 = m0 > 0.0f; p1 = m1 > 0.0f; p2 = m2 > 0.0f; p3 = m3 > 0.0f;
        }
        unsigned b0 = __ballot_sync(0xffffffffu, p0);
        unsigned b1 = __ballot_sync(0xffffffffu, p1);
        unsigned b2 = __ballot_sync(0xffffffffu, p2);
        unsigned b3 = __ballot_sync(0xffffffffu, p3);
        if (lane < 4) {
            int sh = 8 * lane;
            unsigned w = spread8(b0 >> sh)
                       | (spread8(b1 >> sh) << 1)
                       | (spread8(b2 >> sh) << 2)
                       | (spread8(b3 >> sh) << 3);
            int wi = 4 * c + lane;
            if (wi < NWORDS) pos[wi] = w;
        }
        // refill consumed slot with chunk k+DEPTH
        int kn = k + DEPTH;
        if (kn < K) {
            int fn = 32 * (warp + 8 * kn) + lane;
            cpasync16(saddr(&uring[warp][sl][lane]), u4 + fn, fn < NF4);
        }
        CPCOMMIT();
        sl = (sl == DEPTH - 1) ? 0 : sl + 1;
    }
    __syncthreads();

    // ---- Forward reachability R (warp 0, bit-parallel) ----
    if (warp == 0) {
        for (int L = 0; L < NLAY; L++) {
            const int Vq = 2 + 13 * L, b = c_lbase[L];
            unsigned acc1 = 0;
            {
                int s = b + lane * Vq;
                #pragma unroll
                for (int k = 0; k < 5; k++)
                    if (32 * k < Vq) acc1 |= ext32(pos, s + 32 * k) & sR[k];
            }
            bool a2 = false;
            if (lane < 4) {
                unsigned acc2 = 0;
                int s = b + (32 + lane) * Vq;
                #pragma unroll
                for (int k = 0; k < 5; k++)
                    if (32 * k < Vq) acc2 |= ext32(pos, s + 32 * k) & sR[k];
                a2 = acc2 != 0;
            }
            unsigned b1 = __ballot_sync(0xffffffffu, acc1 != 0);
            unsigned b2 = __ballot_sync(0xffffffffu, a2);
            if (lane == 0) {
                #pragma unroll
                for (int h = 0; h < 12; h++) {
                    unsigned q = (b1 >> h) & 1u;
                    unsigned kk = (b1 >> (12 + h)) & 1u;
                    unsigned v = (24 + h < 32) ? ((b1 >> (24 + h)) & 1u)
                                               : ((b2 >> (h - 8)) & 1u);
                    if (q & kk & v) { int p = Vq + h; sR[p >> 5] |= 1u << (p & 31); }
                }
            }
            __syncwarp();
            const int Vm = Vq + 12, sm = b + 36 * Vq;
            bool am = false;
            if (lane < 5 && 32 * lane < Vm)
                am = (ext32(pos, sm + 32 * lane) & sR[lane]) != 0;
            unsigned bm = __ballot_sync(0xffffffffu, am);
            if (lane == 0 && bm) sR[Vm >> 5] |= 1u << (Vm & 31);
            __syncwarp();
        }
        // ---- Backward reachability O on R-pruned graph (keep(R) folded) ----
        if (lane < 5) sO[lane] = ext32(pos, NLM + 32 * lane) & sR[lane] & lenmask(NV - 32 * lane);
        __syncwarp();
        for (int L = NLAY - 1; L >= 0; L--) {
            const int Vq = 2 + 13 * L, b = c_lbase[L], Vm = Vq + 12;
            int obm = getbit(sO, Vm) & getbit(sR, Vm);
            __syncwarp();
            if (obm && lane < 5 && 32 * lane < Vm)
                sO[lane] |= ext32(pos, b + 36 * Vq + 32 * lane) & sR[lane] & lenmask(Vm - 32 * lane);
            __syncwarp();
            unsigned wk[5] = {0, 0, 0, 0, 0};
            {
                int h = Vq + (lane % 12);
                if (getbit(sR, h) & getbit(sO, h)) {
                    int s = b + lane * Vq;
                    #pragma unroll
                    for (int k = 0; k < 5; k++)
                        if (32 * k < Vq) wk[k] = ext32(pos, s + 32 * k) & sR[k] & lenmask(Vq - 32 * k);
                }
            }
            if (lane < 4) {
                int h = Vq + ((32 + lane) % 12);
                if (getbit(sR, h) & getbit(sO, h)) {
                    int s = b + (32 + lane) * Vq;
                    #pragma unroll
                    for (int k = 0; k < 5; k++)
                        if (32 * k < Vq) wk[k] |= ext32(pos, s + 32 * k) & sR[k] & lenmask(Vq - 32 * k);
                }
            }
            #pragma unroll
            for (int k = 0; k < 5; k++) {
                unsigned red = __reduce_or_sync(0xffffffffu, wk[k]);
                if (lane == 0) sO[k] |= red;
            }
            __syncwarp();
        }
    }
    __syncthreads();

    // ---- Single final prune: kill = pos & ~(keepR & keepO) ----
    for (int g = t; g < 449; g += NTHR) {
        if (g < 444) {
            int L = g / 37, r = g % 37;
            int Vq = 2 + 13 * L, b = c_lbase[L];
            int s, len, hv;
            if (r < 36) { s = b + r * Vq; len = Vq; hv = Vq + (r % 12); }
            else        { s = b + 36 * Vq; len = Vq + 12; hv = Vq + 12; }
            int hk = getbit(sR, hv) & getbit(sO, hv);
            for (int k = 0; 32 * k < len; k++) {
                unsigned keep = hk ? (sR[k] & sO[k]) : 0u;
                unsigned kill = ext32(pos, s + 32 * k) & ~keep & lenmask(len - 32 * k);
                while (kill) {
                    int bp = __ffs(kill) - 1; kill &= kill - 1;
                    orow[s + 32 * k + bp] = 0.0f;
                }
            }
        } else {
            int k = g - 444;
            int s = NLM + 32 * k;
            unsigned kill = ext32(pos, s) & ~(sR[k] & sO[k]) & lenmask(NV - 32 * k);
            while (kill) {
                int bp = __ffs(kill) - 1; kill &= kill - 1;
                orow[s + bp] = 0.0f;
            }
        }
    }
}

// ---------------------------------------------------------------------------
extern "C" void kernel_launch(void* const* d_in, const int* in_sizes, int n_in,
                              void* d_out, int out_size) {
    const float* sp   = (const float*)d_in[0];
    const float* unif = (const float*)d_in[1];
    float*       out  = (float*)d_out;
    int bz = in_sizes[1] / NP;

    precompute_kernel<<<(NP + 255) / 256, 256>>>(sp);
    mask_kernel<<<bz, NTHR>>>(unif, out);
}